// round 5
// baseline (speedup 1.0000x reference)
#include <cuda_runtime.h>
#include <cuda_bf16.h>
#include <cstdint>

#define BB 128
#define SS 256
#define II 512
#define HH 1024
#define H3 3072
#define SA 24  // padded smem stride (bf16) -> conflict-free fragment loads
#define NPERS 144

// ---------------- device scratch ----------------
__device__ __align__(16) __nv_bfloat16 g_xhi[(size_t)BB * SS * II];
__device__ __align__(16) __nv_bfloat16 g_xlo[(size_t)BB * SS * II];
__device__ __align__(16) __nv_bfloat16 g_wih_hi[H3 * II];
__device__ __align__(16) __nv_bfloat16 g_wih_lo[H3 * II];
__device__ __align__(16) __nv_bfloat16 g_whh_hi[H3 * HH];
__device__ __align__(16) __nv_bfloat16 g_whh_lo[H3 * HH];
__device__ __align__(16) float g_Xg[(size_t)SS * BB * H3];
__device__ __align__(16) float g_sx[SS * BB];
__device__ __align__(16) float g_hfp[2][BB * HH];
__device__ __align__(16) __nv_bfloat16 g_hhi[2][BB * HH];
__device__ __align__(16) __nv_bfloat16 g_hlo[2][BB * HH];
__device__ __align__(16) float g_ghp[3][(size_t)BB * H3];
__device__ float g_score[2][BB];
__device__ unsigned g_barc;
__device__ unsigned g_barg;

__device__ __forceinline__ void mma16816(float* c, const uint32_t* a, uint32_t b0, uint32_t b1) {
    asm volatile(
        "mma.sync.aligned.m16n8k16.row.col.f32.bf16.bf16.f32 "
        "{%0,%1,%2,%3}, {%4,%5,%6,%7}, {%8,%9}, {%0,%1,%2,%3};\n"
        : "+f"(c[0]), "+f"(c[1]), "+f"(c[2]), "+f"(c[3])
        : "r"(a[0]), "r"(a[1]), "r"(a[2]), "r"(a[3]), "r"(b0), "r"(b1));
}

// device-wide barrier: monotonic generation, arrival=atomicAdd, poll=plain L2 load
__device__ __forceinline__ void gbar(unsigned gen) {
    __syncthreads();
    if (threadIdx.x == 0) {
        __threadfence();
        unsigned t = atomicAdd(&g_barc, 1u) + 1u;
        if (t == gen * NPERS) {
            __threadfence();
            atomicExch(&g_barg, gen);
        } else {
            while (*(volatile unsigned*)&g_barg < gen) __nanosleep(32);
        }
    }
    __syncthreads();
    __threadfence();
}

__device__ __forceinline__ float fsigmoid(float x) { return 1.f / (1.f + __expf(-x)); }
__device__ __forceinline__ float ftanh(float x) { float e = __expf(2.f * x); return 1.f - 2.f / (e + 1.f); }

// ---------------- init ----------------
__global__ void k_init() {
    int i = blockIdx.x * blockDim.x + threadIdx.x;
    if (i < BB * HH) {
        g_hfp[1][i] = 0.f;
        g_hhi[1][i] = __float2bfloat16(0.f);
        g_hlo[1][i] = __float2bfloat16(0.f);
    }
    if (i < BB) g_score[1][i] = 0.f;
    if (i == 0) { g_barc = 0u; g_barg = 0u; }
}

// ---------------- fp32 -> bf16 hi/lo split ----------------
__global__ void k_split(const float* __restrict__ src, int n, int which) {
    __nv_bfloat16 *hi, *lo;
    if (which == 0)      { hi = g_xhi;    lo = g_xlo; }
    else if (which == 1) { hi = g_wih_hi; lo = g_wih_lo; }
    else                 { hi = g_whh_hi; lo = g_whh_lo; }
    int i = blockIdx.x * blockDim.x + threadIdx.x;
    if (i < n) {
        float v = src[i];
        __nv_bfloat16 h = __float2bfloat16(v);
        hi[i] = h;
        lo[i] = __float2bfloat16(v - __bfloat162float(h));
    }
}

// ---------------- sx[t][b] = x[b,t,:] . W_att[0:I] ----------------
__global__ void k_sx(const float* __restrict__ x, const float* __restrict__ Watt) {
    int gw = (blockIdx.x * blockDim.x + threadIdx.x) >> 5;
    int lane = threadIdx.x & 31;
    if (gw >= SS * BB) return;
    int t = gw >> 7, b = gw & 127;
    const float* xr = x + ((size_t)b * SS + t) * II;
    float s = 0.f;
    for (int k = lane; k < II; k += 32) s += xr[k] * Watt[k];
    #pragma unroll
    for (int o = 16; o; o >>= 1) s += __shfl_xor_sync(0xffffffffu, s, o);
    if (!lane) g_sx[gw] = s;
}

// ---------------- precompute Xg[t][b][:] = x_t @ W_ih^T (3-way split) ----------------
__global__ __launch_bounds__(256) void k_xg() {
    __shared__ __align__(16) __nv_bfloat16 As[2][128 * SA];
    __shared__ __align__(16) __nv_bfloat16 Bs[2][128 * SA];
    const int nblk = blockIdx.x, t = blockIdx.y;
    const int tid = threadIdx.x, w = tid >> 5, lane = tid & 31;
    const int wm = w & 3, wn = w >> 2, gid = lane >> 2, tig = lane & 3;
    const int ar = tid >> 1, ah = tid & 1;
    const size_t a_base = ((size_t)ar * SS + t) * II + ah * 8;
    const size_t b_base = ((size_t)(nblk * 128 + ar)) * II + ah * 8;

    float acc[2][8][4];
    #pragma unroll
    for (int i = 0; i < 2; ++i)
        #pragma unroll
        for (int j = 0; j < 8; ++j) { acc[i][j][0]=acc[i][j][1]=acc[i][j][2]=acc[i][j][3]=0.f; }

    *(uint4*)&As[0][ar * SA + ah * 8] = *(const uint4*)(g_xhi + a_base);
    *(uint4*)&Bs[0][ar * SA + ah * 8] = *(const uint4*)(g_wih_hi + b_base);
    __syncthreads();

    for (int it = 0; it < 96; ++it) {
        const int cur = it & 1;
        uint4 va, vb;
        const bool pf = (it + 1 < 96);
        if (pf) {
            int it2 = it + 1, seg = it2 >> 5, kk = (it2 & 31) << 4;
            const __nv_bfloat16* pa = (seg == 1) ? g_xlo : g_xhi;
            const __nv_bfloat16* pb = (seg == 2) ? g_wih_lo : g_wih_hi;
            va = *(const uint4*)(pa + a_base + kk);
            vb = *(const uint4*)(pb + b_base + kk);
        }
        uint32_t af[2][4];
        #pragma unroll
        for (int mt = 0; mt < 2; ++mt) {
            int r0 = wm * 32 + mt * 16;
            af[mt][0] = *(const uint32_t*)&As[cur][(r0 + gid) * SA + 2 * tig];
            af[mt][1] = *(const uint32_t*)&As[cur][(r0 + gid + 8) * SA + 2 * tig];
            af[mt][2] = *(const uint32_t*)&As[cur][(r0 + gid) * SA + 2 * tig + 8];
            af[mt][3] = *(const uint32_t*)&As[cur][(r0 + gid + 8) * SA + 2 * tig + 8];
        }
        #pragma unroll
        for (int nt = 0; nt < 8; ++nt) {
            int n0 = (wn * 8 + nt) * 8;
            uint32_t b0 = *(const uint32_t*)&Bs[cur][(n0 + gid) * SA + 2 * tig];
            uint32_t b1 = *(const uint32_t*)&Bs[cur][(n0 + gid) * SA + 2 * tig + 8];
            mma16816(acc[0][nt], af[0], b0, b1);
            mma16816(acc[1][nt], af[1], b0, b1);
        }
        __syncthreads();
        if (pf) {
            int nb = (it + 1) & 1;
            *(uint4*)&As[nb][ar * SA + ah * 8] = va;
            *(uint4*)&Bs[nb][ar * SA + ah * 8] = vb;
            __syncthreads();
        }
    }
    #pragma unroll
    for (int mt = 0; mt < 2; ++mt)
        #pragma unroll
        for (int nt = 0; nt < 8; ++nt) {
            int m = wm * 32 + mt * 16 + gid;
            int n = nblk * 128 + wn * 64 + nt * 8 + 2 * tig;
            size_t base = ((size_t)t * BB + m) * H3 + n;
            g_Xg[base]            = acc[mt][nt][0];
            g_Xg[base + 1]        = acc[mt][nt][1];
            g_Xg[base + 8 * H3]   = acc[mt][nt][2];
            g_Xg[base + 8 * H3+1] = acc[mt][nt][3];
        }
}

// ---------------- persistent step kernel: all 256 steps ----------------
// Phase A: 144 blocks = 48 n-tiles(64 cols) x 3 segs, full K=1024.
// Phase B: blocks 0..127 (one per batch row).
__global__ __launch_bounds__(256) void k_steps(const float* __restrict__ Watt,
                                               const float* __restrict__ b_ih,
                                               const float* __restrict__ b_hh,
                                               float* __restrict__ out, long long out_sz) {
    __shared__ __align__(16) __nv_bfloat16 As[2][128 * SA];
    __shared__ __align__(16) __nv_bfloat16 Bs[2][64 * SA];
    __shared__ float sc[BB], red[BB], wsum[8];

    const int bid = blockIdx.x;
    const int tid = threadIdx.x, w = tid >> 5, lane = tid & 31;
    const int wm = w & 3, wn = w >> 2, gid = lane >> 2, tig = lane & 3;
    const int ar = tid >> 1, ah = tid & 1;

    // phase-A mapping
    const int nblk = bid % 48;
    const int seg = bid / 48;   // 0..2
    const __nv_bfloat16* Bp = (seg == 2) ? g_whh_lo : g_whh_hi;
    const size_t a_off = (size_t)ar * HH + ah * 8;
    const size_t b_base = (size_t)(nblk * 64 + ar) * HH + ah * 8;  // valid when ar<64
    const bool bvalid = (ar < 64);

    // phase-B loop invariants
    const int j = tid * 4;
    float brz[8], bnn[8], wat[4];
    #pragma unroll
    for (int u = 0; u < 4; ++u) {
        brz[u]     = b_ih[j + u] + b_hh[j + u];             // r-gate combined bias
        brz[4 + u] = b_ih[HH + j + u] + b_hh[HH + j + u];   // z-gate combined bias
        bnn[u]     = b_ih[2 * HH + j + u];                  // n-gate input bias
        bnn[4 + u] = b_hh[2 * HH + j + u];                  // n-gate hidden bias
        wat[u]     = Watt[II + j + u];
    }

    unsigned gen = 0;
    for (int t = 0; t < SS; ++t) {
        const int pin = (t + 1) & 1, pout = t & 1;

        // ---------- phase A: gh partials = h @ W_hh^T (3 segs) ----------
        {
            const __nv_bfloat16* Ap = (seg == 1) ? g_hlo[pin] : g_hhi[pin];

            float acc[2][4][4];
            #pragma unroll
            for (int i = 0; i < 2; ++i)
                #pragma unroll
                for (int jj = 0; jj < 4; ++jj) { acc[i][jj][0]=acc[i][jj][1]=acc[i][jj][2]=acc[i][jj][3]=0.f; }

            *(uint4*)&As[0][ar * SA + ah * 8] = __ldcg((const uint4*)(Ap + a_off));
            if (bvalid) *(uint4*)&Bs[0][ar * SA + ah * 8] = *(const uint4*)(Bp + b_base);
            __syncthreads();

            for (int it = 0; it < 64; ++it) {
                const int cur = it & 1;
                uint4 va, vb;
                const bool pf = (it + 1 < 64);
                if (pf) {
                    int kk = (it + 1) << 4;
                    va = __ldcg((const uint4*)(Ap + a_off + kk));
                    if (bvalid) vb = *(const uint4*)(Bp + b_base + kk);
                }
                uint32_t af[2][4];
                #pragma unroll
                for (int mt = 0; mt < 2; ++mt) {
                    int r0 = wm * 32 + mt * 16;
                    af[mt][0] = *(const uint32_t*)&As[cur][(r0 + gid) * SA + 2 * tig];
                    af[mt][1] = *(const uint32_t*)&As[cur][(r0 + gid + 8) * SA + 2 * tig];
                    af[mt][2] = *(const uint32_t*)&As[cur][(r0 + gid) * SA + 2 * tig + 8];
                    af[mt][3] = *(const uint32_t*)&As[cur][(r0 + gid + 8) * SA + 2 * tig + 8];
                }
                #pragma unroll
                for (int nt = 0; nt < 4; ++nt) {
                    int n0 = wn * 32 + nt * 8;
                    uint32_t b0 = *(const uint32_t*)&Bs[cur][(n0 + gid) * SA + 2 * tig];
                    uint32_t b1 = *(const uint32_t*)&Bs[cur][(n0 + gid) * SA + 2 * tig + 8];
                    mma16816(acc[0][nt], af[0], b0, b1);
                    mma16816(acc[1][nt], af[1], b0, b1);
                }
                __syncthreads();
                if (pf) {
                    int nb = (it + 1) & 1;
                    *(uint4*)&As[nb][ar * SA + ah * 8] = va;
                    if (bvalid) *(uint4*)&Bs[nb][ar * SA + ah * 8] = vb;
                    __syncthreads();
                }
            }
            float* o = g_ghp[seg];
            #pragma unroll
            for (int mt = 0; mt < 2; ++mt)
                #pragma unroll
                for (int nt = 0; nt < 4; ++nt) {
                    int m = wm * 32 + mt * 16 + gid;
                    int n = nblk * 64 + wn * 32 + nt * 8 + 2 * tig;
                    size_t base = (size_t)m * H3 + n;
                    __stcg(&o[base],            acc[mt][nt][0]);
                    __stcg(&o[base + 1],        acc[mt][nt][1]);
                    __stcg(&o[base + 8 * H3],   acc[mt][nt][2]);
                    __stcg(&o[base + 8 * H3+1], acc[mt][nt][3]);
                }
        }
        gbar(++gen);

        // ---------- phase B: softmax + partial-sum + GRU update ----------
        if (bid < BB) {
            const int b = bid;
            if (tid < BB) {
                float v = __ldcg(&g_score[pin][tid]) + g_sx[t * BB + tid];
                sc[tid] = v;
                red[tid] = v;
            }
            __syncthreads();
            for (int s = 64; s; s >>= 1) { if (tid < s) red[tid] = fmaxf(red[tid], red[tid + s]); __syncthreads(); }
            float mx = red[0];
            __syncthreads();
            if (tid < BB) red[tid] = __expf(sc[tid] - mx);
            __syncthreads();
            for (int s = 64; s; s >>= 1) { if (tid < s) red[tid] += red[tid + s]; __syncthreads(); }
            const float att = __expf(sc[b] - mx) / red[0];

            const size_t rowb = (size_t)b * H3;
            float4 gr = make_float4(0, 0, 0, 0), gz = gr, gn = gr;
            #pragma unroll
            for (int c = 0; c < 3; ++c) {
                float4 v;
                v = __ldcg((const float4*)&g_ghp[c][rowb + j]);        gr.x+=v.x; gr.y+=v.y; gr.z+=v.z; gr.w+=v.w;
                v = __ldcg((const float4*)&g_ghp[c][rowb + HH + j]);   gz.x+=v.x; gz.y+=v.y; gz.z+=v.z; gz.w+=v.w;
                v = __ldcg((const float4*)&g_ghp[c][rowb + 2*HH + j]); gn.x+=v.x; gn.y+=v.y; gn.z+=v.z; gn.w+=v.w;
            }
            const size_t xgb = ((size_t)t * BB + b) * H3;
            float4 xr = *(const float4*)&g_Xg[xgb + j];
            float4 xz = *(const float4*)&g_Xg[xgb + HH + j];
            float4 xn = *(const float4*)&g_Xg[xgb + 2*HH + j];
            float4 hp = __ldcg((const float4*)&g_hfp[pin][(size_t)b * HH + j]);

            float hn[4], hdot = 0.f;
            #pragma unroll
            for (int u = 0; u < 4; ++u) {
                float r = fsigmoid(att * ((&xr.x)[u]) + (&gr.x)[u] + brz[u]);
                float z = fsigmoid(att * ((&xz.x)[u]) + (&gz.x)[u] + brz[4 + u]);
                float n = ftanh(att * ((&xn.x)[u]) + bnn[u] + r * ((&gn.x)[u] + bnn[4 + u]));
                float h = (1.f - z) * n + z * (&hp.x)[u];
                hn[u] = h;
                hdot += h * wat[u];
            }
            *(float4*)&out[((size_t)b * SS + t) * HH + j] = make_float4(hn[0], hn[1], hn[2], hn[3]);
            if (t == SS - 1 && out_sz >= (long long)BB * SS * HH + BB * HH)
                *(float4*)&out[(size_t)BB * SS * HH + (size_t)b * HH + j] = make_float4(hn[0], hn[1], hn[2], hn[3]);

            float4 hv = make_float4(hn[0], hn[1], hn[2], hn[3]);
            __stcg((float4*)&g_hfp[pout][(size_t)b * HH + j], hv);
            __nv_bfloat16 hi4[4], lo4[4];
            #pragma unroll
            for (int u = 0; u < 4; ++u) {
                hi4[u] = __float2bfloat16(hn[u]);
                lo4[u] = __float2bfloat16(hn[u] - __bfloat162float(hi4[u]));
            }
            __stcg((uint2*)&g_hhi[pout][(size_t)b * HH + j], *(uint2*)hi4);
            __stcg((uint2*)&g_hlo[pout][(size_t)b * HH + j], *(uint2*)lo4);

            #pragma unroll
            for (int o = 16; o; o >>= 1) hdot += __shfl_xor_sync(0xffffffffu, hdot, o);
            if ((tid & 31) == 0) wsum[tid >> 5] = hdot;
            __syncthreads();
            if (tid == 0) {
                float s = 0.f;
                #pragma unroll
                for (int i = 0; i < 8; ++i) s += wsum[i];
                __stcg(&g_score[pout][b], s);
            }
        }
        gbar(++gen);
    }
}

// ---------------- launch ----------------
extern "C" void kernel_launch(void* const* d_in, const int* in_sizes, int n_in,
                              void* d_out, int out_size) {
    const float* x    = (const float*)d_in[0];
    const float* Watt = (const float*)d_in[1];
    const float* Wih  = (const float*)d_in[3];
    const float* Whh  = (const float*)d_in[4];
    const float* b_ih = (const float*)d_in[5];
    const float* b_hh = (const float*)d_in[6];
    float* out = (float*)d_out;

    k_split<<<(BB * SS * II + 255) / 256, 256>>>(x, BB * SS * II, 0);
    k_split<<<(H3 * II + 255) / 256, 256>>>(Wih, H3 * II, 1);
    k_split<<<(H3 * HH + 255) / 256, 256>>>(Whh, H3 * HH, 2);
    k_sx<<<4096, 256>>>(x, Watt);
    k_init<<<512, 256>>>();
    k_xg<<<dim3(24, 256), 256>>>();
    k_steps<<<NPERS, 256>>>(Watt, b_ih, b_hh, out, (long long)out_size);
}

// round 11
// speedup vs baseline: 1.5093x; 1.5093x over previous
#include <cuda_runtime.h>
#include <cuda_bf16.h>
#include <cstdint>

#define BB 128
#define SS 256
#define II 512
#define HH 1024
#define H3 3072
#define SA 24    // padded smem stride for k_xg tiles
#define NPERS 144
#define BST 1032 // B-resident smem row stride (bf16): conflict-free
#define AST 72   // A-chunk smem row stride (bf16): conflict-free

// dynamic smem layout for k_steps
#define BSM_BYTES (64 * BST * 2)          // 132096
#define ASM_BYTES (2 * 128 * AST * 2)     // 36864
#define SMEM_STEPS (BSM_BYTES + ASM_BYTES + 264 * 4)

// ---------------- device scratch ----------------
__device__ __align__(16) __nv_bfloat16 g_xhi[(size_t)BB * SS * II];
__device__ __align__(16) __nv_bfloat16 g_xlo[(size_t)BB * SS * II];
__device__ __align__(16) __nv_bfloat16 g_wih_hi[H3 * II];
__device__ __align__(16) __nv_bfloat16 g_wih_lo[H3 * II];
__device__ __align__(16) __nv_bfloat16 g_whh_hi[H3 * HH];
__device__ __align__(16) __nv_bfloat16 g_whh_lo[H3 * HH];
__device__ __align__(16) float g_Xg[(size_t)SS * BB * H3];
__device__ __align__(16) float g_sx[SS * BB];
__device__ __align__(16) float g_hfp[2][BB * HH];
__device__ __align__(16) __nv_bfloat16 g_hhi[2][BB * HH];
__device__ __align__(16) __nv_bfloat16 g_hlo[2][BB * HH];
__device__ __align__(16) float g_ghp[3][(size_t)BB * H3];
__device__ float g_score[2][BB];
__device__ unsigned g_barc;
__device__ unsigned g_barg;

__device__ __forceinline__ void mma16816(float* c, const uint32_t* a, uint32_t b0, uint32_t b1) {
    asm volatile(
        "mma.sync.aligned.m16n8k16.row.col.f32.bf16.bf16.f32 "
        "{%0,%1,%2,%3}, {%4,%5,%6,%7}, {%8,%9}, {%0,%1,%2,%3};\n"
        : "+f"(c[0]), "+f"(c[1]), "+f"(c[2]), "+f"(c[3])
        : "r"(a[0]), "r"(a[1]), "r"(a[2]), "r"(a[3]), "r"(b0), "r"(b1));
}

// device-wide barrier: arrival = one atomicAdd; poll = volatile L2 load with
// nanosleep backoff; release = monotonic generation store. No RMW poll storm,
// no counter-reset race.
__device__ __forceinline__ void gbar(unsigned gen) {
    __syncthreads();
    if (threadIdx.x == 0) {
        __threadfence();
        unsigned t = atomicAdd(&g_barc, 1u) + 1u;
        if (t == gen * NPERS) {
            atomicExch(&g_barg, gen);
        } else {
            while (((volatile unsigned*)&g_barg)[0] < gen) __nanosleep(32);
        }
    }
    __syncthreads();
    __threadfence();
}

__device__ __forceinline__ float fsigmoid(float x) { return 1.f / (1.f + __expf(-x)); }
__device__ __forceinline__ float ftanh(float x) { float e = __expf(2.f * x); return 1.f - 2.f / (e + 1.f); }

// ---------------- init ----------------
__global__ void k_init() {
    int i = blockIdx.x * blockDim.x + threadIdx.x;
    if (i < BB * HH) {
        g_hfp[1][i] = 0.f;
        g_hhi[1][i] = __float2bfloat16(0.f);
        g_hlo[1][i] = __float2bfloat16(0.f);
    }
    if (i < BB) g_score[1][i] = 0.f;
    if (i == 0) { g_barc = 0u; g_barg = 0u; }
}

// ---------------- fp32 -> bf16 hi/lo split ----------------
__global__ void k_split(const float* __restrict__ src, int n, int which) {
    __nv_bfloat16 *hi, *lo;
    if (which == 0)      { hi = g_xhi;    lo = g_xlo; }
    else if (which == 1) { hi = g_wih_hi; lo = g_wih_lo; }
    else                 { hi = g_whh_hi; lo = g_whh_lo; }
    int i = blockIdx.x * blockDim.x + threadIdx.x;
    if (i < n) {
        float v = src[i];
        __nv_bfloat16 h = __float2bfloat16(v);
        hi[i] = h;
        lo[i] = __float2bfloat16(v - __bfloat162float(h));
    }
}

// ---------------- sx[t][b] = x[b,t,:] . W_att[0:I] ----------------
__global__ void k_sx(const float* __restrict__ x, const float* __restrict__ Watt) {
    int gw = (blockIdx.x * blockDim.x + threadIdx.x) >> 5;
    int lane = threadIdx.x & 31;
    if (gw >= SS * BB) return;
    int t = gw >> 7, b = gw & 127;
    const float* xr = x + ((size_t)b * SS + t) * II;
    float s = 0.f;
    for (int k = lane; k < II; k += 32) s += xr[k] * Watt[k];
    #pragma unroll
    for (int o = 16; o; o >>= 1) s += __shfl_xor_sync(0xffffffffu, s, o);
    if (!lane) g_sx[gw] = s;
}

// ---------------- precompute Xg[t][b][:] = x_t @ W_ih^T (3-way split) ----------------
__global__ __launch_bounds__(256) void k_xg() {
    __shared__ __align__(16) __nv_bfloat16 As[2][128 * SA];
    __shared__ __align__(16) __nv_bfloat16 Bs[2][128 * SA];
    const int nblk = blockIdx.x, t = blockIdx.y;
    const int tid = threadIdx.x, w = tid >> 5, lane = tid & 31;
    const int wm = w & 3, wn = w >> 2, gid = lane >> 2, tig = lane & 3;
    const int ar = tid >> 1, ah = tid & 1;
    const size_t a_base = ((size_t)ar * SS + t) * II + ah * 8;
    const size_t b_base = ((size_t)(nblk * 128 + ar)) * II + ah * 8;

    float acc[2][8][4];
    #pragma unroll
    for (int i = 0; i < 2; ++i)
        #pragma unroll
        for (int j = 0; j < 8; ++j) { acc[i][j][0]=acc[i][j][1]=acc[i][j][2]=acc[i][j][3]=0.f; }

    *(uint4*)&As[0][ar * SA + ah * 8] = *(const uint4*)(g_xhi + a_base);
    *(uint4*)&Bs[0][ar * SA + ah * 8] = *(const uint4*)(g_wih_hi + b_base);
    __syncthreads();

    for (int it = 0; it < 96; ++it) {
        const int cur = it & 1;
        uint4 va, vb;
        const bool pf = (it + 1 < 96);
        if (pf) {
            int it2 = it + 1, seg = it2 >> 5, kk = (it2 & 31) << 4;
            const __nv_bfloat16* pa = (seg == 1) ? g_xlo : g_xhi;
            const __nv_bfloat16* pb = (seg == 2) ? g_wih_lo : g_wih_hi;
            va = *(const uint4*)(pa + a_base + kk);
            vb = *(const uint4*)(pb + b_base + kk);
        }
        uint32_t af[2][4];
        #pragma unroll
        for (int mt = 0; mt < 2; ++mt) {
            int r0 = wm * 32 + mt * 16;
            af[mt][0] = *(const uint32_t*)&As[cur][(r0 + gid) * SA + 2 * tig];
            af[mt][1] = *(const uint32_t*)&As[cur][(r0 + gid + 8) * SA + 2 * tig];
            af[mt][2] = *(const uint32_t*)&As[cur][(r0 + gid) * SA + 2 * tig + 8];
            af[mt][3] = *(const uint32_t*)&As[cur][(r0 + gid + 8) * SA + 2 * tig + 8];
        }
        #pragma unroll
        for (int nt = 0; nt < 8; ++nt) {
            int n0 = (wn * 8 + nt) * 8;
            uint32_t b0 = *(const uint32_t*)&Bs[cur][(n0 + gid) * SA + 2 * tig];
            uint32_t b1 = *(const uint32_t*)&Bs[cur][(n0 + gid) * SA + 2 * tig + 8];
            mma16816(acc[0][nt], af[0], b0, b1);
            mma16816(acc[1][nt], af[1], b0, b1);
        }
        __syncthreads();
        if (pf) {
            int nb = (it + 1) & 1;
            *(uint4*)&As[nb][ar * SA + ah * 8] = va;
            *(uint4*)&Bs[nb][ar * SA + ah * 8] = vb;
            __syncthreads();
        }
    }
    #pragma unroll
    for (int mt = 0; mt < 2; ++mt)
        #pragma unroll
        for (int nt = 0; nt < 8; ++nt) {
            int m = wm * 32 + mt * 16 + gid;
            int n = nblk * 128 + wn * 64 + nt * 8 + 2 * tig;
            size_t base = ((size_t)t * BB + m) * H3 + n;
            g_Xg[base]            = acc[mt][nt][0];
            g_Xg[base + 1]        = acc[mt][nt][1];
            g_Xg[base + 8 * H3]   = acc[mt][nt][2];
            g_Xg[base + 8 * H3+1] = acc[mt][nt][3];
        }
}

// ---------------- persistent step kernel ----------------
// Phase A: 144 blocks = 48 n-tiles(64) x 3 segs. W_hh tile RESIDENT in smem across
// all steps; h streams through a 2-buffer 64-wide k-chunk pipeline (1 sync/chunk).
// Phase B: blocks 0..127, one per batch row.
__global__ __launch_bounds__(256) void k_steps(const float* __restrict__ Watt,
                                               const float* __restrict__ b_ih,
                                               const float* __restrict__ b_hh,
                                               float* __restrict__ out, long long out_sz) {
    extern __shared__ __align__(16) char smem[];
    __nv_bfloat16* Bsm = (__nv_bfloat16*)smem;                       // 64 x BST
    __nv_bfloat16* Asm = (__nv_bfloat16*)(smem + BSM_BYTES);         // 2 x 128 x AST
    float* sc   = (float*)(smem + BSM_BYTES + ASM_BYTES);
    float* red  = sc + 128;
    float* wsum = red + 128;

    const int bid = blockIdx.x;
    const int tid = threadIdx.x, w = tid >> 5, lane = tid & 31;
    const int wm = w & 3, wn = w >> 2, gid = lane >> 2, tig = lane & 3;

    // phase-A mapping
    const int nblk = bid % 48;
    const int seg = bid / 48;   // 0..2
    const __nv_bfloat16* Bp = (seg == 2) ? g_whh_lo : g_whh_hi;
    const int ar2 = tid >> 1, half = tid & 1;

    // ---- load resident W_hh tile: 64 rows x 1024 cols ----
    for (int i = tid; i < 64 * 128; i += 256) {
        int r = i >> 7, c = i & 127;
        *(uint4*)&Bsm[r * BST + c * 8] =
            *(const uint4*)(Bp + (size_t)(nblk * 64 + r) * HH + c * 8);
    }

    // phase-B loop invariants
    const int j = tid * 4;
    float brz[8], bnn[8], wat[4];
    #pragma unroll
    for (int u = 0; u < 4; ++u) {
        brz[u]     = b_ih[j + u] + b_hh[j + u];
        brz[4 + u] = b_ih[HH + j + u] + b_hh[HH + j + u];
        bnn[u]     = b_ih[2 * HH + j + u];
        bnn[4 + u] = b_hh[2 * HH + j + u];
        wat[u]     = Watt[II + j + u];
    }
    __syncthreads();

    unsigned gen = 0;
    for (int t = 0; t < SS; ++t) {
        const int pin = (t + 1) & 1, pout = t & 1;

        // ---------- phase A ----------
        {
            const __nv_bfloat16* Ap = (seg == 1) ? g_hlo[pin] : g_hhi[pin];
            const size_t arow = (size_t)ar2 * HH + half * 32;

            float acc[2][4][4];
            #pragma unroll
            for (int i = 0; i < 2; ++i)
                #pragma unroll
                for (int jj = 0; jj < 4; ++jj) { acc[i][jj][0]=acc[i][jj][1]=acc[i][jj][2]=acc[i][jj][3]=0.f; }

            // prologue: chunk 0 -> buf 0
            {
                uint4 p0 = __ldcg((const uint4*)(Ap + arow));
                uint4 p1 = __ldcg((const uint4*)(Ap + arow + 8));
                uint4 p2 = __ldcg((const uint4*)(Ap + arow + 16));
                uint4 p3 = __ldcg((const uint4*)(Ap + arow + 24));
                __nv_bfloat16* d = &Asm[ar2 * AST + half * 32];
                *(uint4*)(d)      = p0;
                *(uint4*)(d + 8)  = p1;
                *(uint4*)(d + 16) = p2;
                *(uint4*)(d + 24) = p3;
            }
            __syncthreads();

            #pragma unroll 1
            for (int kc = 0; kc < 16; ++kc) {
                const int cur = kc & 1;
                uint4 p0, p1, p2, p3;
                const bool pf = (kc < 15);
                if (pf) {
                    const __nv_bfloat16* s = Ap + arow + (kc + 1) * 64;
                    p0 = __ldcg((const uint4*)(s));
                    p1 = __ldcg((const uint4*)(s + 8));
                    p2 = __ldcg((const uint4*)(s + 16));
                    p3 = __ldcg((const uint4*)(s + 24));
                }
                #pragma unroll
                for (int ks = 0; ks < 4; ++ks) {
                    const int ko = ks * 16;
                    uint32_t af[2][4];
                    #pragma unroll
                    for (int mt = 0; mt < 2; ++mt) {
                        const __nv_bfloat16* ab = &Asm[cur * (128 * AST) + (wm * 32 + mt * 16 + gid) * AST + 2 * tig + ko];
                        af[mt][0] = *(const uint32_t*)(ab);
                        af[mt][1] = *(const uint32_t*)(ab + 8 * AST);
                        af[mt][2] = *(const uint32_t*)(ab + 8);
                        af[mt][3] = *(const uint32_t*)(ab + 8 * AST + 8);
                    }
                    #pragma unroll
                    for (int nt = 0; nt < 4; ++nt) {
                        const __nv_bfloat16* bb = &Bsm[(wn * 32 + nt * 8 + gid) * BST + kc * 64 + ko + 2 * tig];
                        uint32_t b0 = *(const uint32_t*)(bb);
                        uint32_t b1 = *(const uint32_t*)(bb + 8);
                        mma16816(acc[0][nt], af[0], b0, b1);
                        mma16816(acc[1][nt], af[1], b0, b1);
                    }
                }
                if (pf) {
                    __nv_bfloat16* d = &Asm[(cur ^ 1) * (128 * AST) + ar2 * AST + half * 32];
                    *(uint4*)(d)      = p0;
                    *(uint4*)(d + 8)  = p1;
                    *(uint4*)(d + 16) = p2;
                    *(uint4*)(d + 24) = p3;
                }
                __syncthreads();
            }
            float* o = g_ghp[seg];
            #pragma unroll
            for (int mt = 0; mt < 2; ++mt)
                #pragma unroll
                for (int nt = 0; nt < 4; ++nt) {
                    int m = wm * 32 + mt * 16 + gid;
                    int n = nblk * 64 + wn * 32 + nt * 8 + 2 * tig;
                    size_t base = (size_t)m * H3 + n;
                    __stcg(&o[base],            acc[mt][nt][0]);
                    __stcg(&o[base + 1],        acc[mt][nt][1]);
                    __stcg(&o[base + 8 * H3],   acc[mt][nt][2]);
                    __stcg(&o[base + 8 * H3+1], acc[mt][nt][3]);
                }
        }
        gbar(++gen);

        // ---------- phase B ----------
        if (bid < BB) {
            const int b = bid;
            if (tid < BB) {
                float v = __ldcg(&g_score[pin][tid]) + g_sx[t * BB + tid];
                sc[tid] = v;
                red[tid] = v;
            }
            __syncthreads();
            for (int s = 64; s; s >>= 1) { if (tid < s) red[tid] = fmaxf(red[tid], red[tid + s]); __syncthreads(); }
            float mx = red[0];
            __syncthreads();
            if (tid < BB) red[tid] = __expf(sc[tid] - mx);
            __syncthreads();
            for (int s = 64; s; s >>= 1) { if (tid < s) red[tid] += red[tid + s]; __syncthreads(); }
            const float att = __expf(sc[b] - mx) / red[0];

            const size_t rowb = (size_t)b * H3;
            float4 gr = make_float4(0, 0, 0, 0), gz = gr, gn = gr;
            #pragma unroll
            for (int c = 0; c < 3; ++c) {
                float4 v;
                v = __ldcg((const float4*)&g_ghp[c][rowb + j]);        gr.x+=v.x; gr.y+=v.y; gr.z+=v.z; gr.w+=v.w;
                v = __ldcg((const float4*)&g_ghp[c][rowb + HH + j]);   gz.x+=v.x; gz.y+=v.y; gz.z+=v.z; gz.w+=v.w;
                v = __ldcg((const float4*)&g_ghp[c][rowb + 2*HH + j]); gn.x+=v.x; gn.y+=v.y; gn.z+=v.z; gn.w+=v.w;
            }
            const size_t xgb = ((size_t)t * BB + b) * H3;
            float4 xr = *(const float4*)&g_Xg[xgb + j];
            float4 xz = *(const float4*)&g_Xg[xgb + HH + j];
            float4 xn = *(const float4*)&g_Xg[xgb + 2*HH + j];
            float4 hp = __ldcg((const float4*)&g_hfp[pin][(size_t)b * HH + j]);

            float hn[4], hdot = 0.f;
            #pragma unroll
            for (int u = 0; u < 4; ++u) {
                float r = fsigmoid(att * ((&xr.x)[u]) + (&gr.x)[u] + brz[u]);
                float z = fsigmoid(att * ((&xz.x)[u]) + (&gz.x)[u] + brz[4 + u]);
                float n = ftanh(att * ((&xn.x)[u]) + bnn[u] + r * ((&gn.x)[u] + bnn[4 + u]));
                float h = (1.f - z) * n + z * (&hp.x)[u];
                hn[u] = h;
                hdot += h * wat[u];
            }
            *(float4*)&out[((size_t)b * SS + t) * HH + j] = make_float4(hn[0], hn[1], hn[2], hn[3]);
            if (t == SS - 1 && out_sz >= (long long)BB * SS * HH + BB * HH)
                *(float4*)&out[(size_t)BB * SS * HH + (size_t)b * HH + j] = make_float4(hn[0], hn[1], hn[2], hn[3]);

            float4 hv = make_float4(hn[0], hn[1], hn[2], hn[3]);
            __stcg((float4*)&g_hfp[pout][(size_t)b * HH + j], hv);
            __nv_bfloat16 hi4[4], lo4[4];
            #pragma unroll
            for (int u = 0; u < 4; ++u) {
                hi4[u] = __float2bfloat16(hn[u]);
                lo4[u] = __float2bfloat16(hn[u] - __bfloat162float(hi4[u]));
            }
            __stcg((uint2*)&g_hhi[pout][(size_t)b * HH + j], *(uint2*)hi4);
            __stcg((uint2*)&g_hlo[pout][(size_t)b * HH + j], *(uint2*)lo4);

            #pragma unroll
            for (int o = 16; o; o >>= 1) hdot += __shfl_xor_sync(0xffffffffu, hdot, o);
            if ((tid & 31) == 0) wsum[tid >> 5] = hdot;
            __syncthreads();
            if (tid == 0) {
                float s = 0.f;
                #pragma unroll
                for (int i = 0; i < 8; ++i) s += wsum[i];
                __stcg(&g_score[pout][b], s);
            }
        }
        gbar(++gen);
    }
}

// ---------------- launch ----------------
extern "C" void kernel_launch(void* const* d_in, const int* in_sizes, int n_in,
                              void* d_out, int out_size) {
    const float* x    = (const float*)d_in[0];
    const float* Watt = (const float*)d_in[1];
    const float* Wih  = (const float*)d_in[3];
    const float* Whh  = (const float*)d_in[4];
    const float* b_ih = (const float*)d_in[5];
    const float* b_hh = (const float*)d_in[6];
    float* out = (float*)d_out;

    // Unconditional (deterministic, idempotent, not a stream operation).
    cudaFuncSetAttribute(k_steps, cudaFuncAttributeMaxDynamicSharedMemorySize, SMEM_STEPS);

    k_split<<<(BB * SS * II + 255) / 256, 256>>>(x, BB * SS * II, 0);
    k_split<<<(H3 * II + 255) / 256, 256>>>(Wih, H3 * II, 1);
    k_split<<<(H3 * HH + 255) / 256, 256>>>(Whh, H3 * HH, 2);
    k_sx<<<4096, 256>>>(x, Watt);
    k_init<<<512, 256>>>();
    k_xg<<<dim3(24, 256), 256>>>();
    k_steps<<<NPERS, 256, SMEM_STEPS>>>(Watt, b_ih, b_hh, out, (long long)out_size);
}

// round 15
// speedup vs baseline: 2.6312x; 1.7433x over previous
#include <cuda_runtime.h>
#include <cuda_fp16.h>
#include <cstdint>

#define BB 128
#define SS 256
#define II 512
#define HH 1024
#define H3 3072
#define SA 24     // padded smem stride for k_xg tiles (fp16 elems)
#define NPERS 128
#define BST2 520  // resident W tile row stride (fp16): 1040B, conflict-free
#define AST 72    // h chunk row stride (fp16): 144B, conflict-free

// dynamic smem offsets for k_steps
#define TILB_OFF 0                       // 48 x 520 fp16 = 49920
#define ABUF_OFF 49920                   // 2 x 128 x 72 fp16 = 36864
#define SC_OFF   86784
#define RED_OFF  87296
#define WSUM_OFF 87808
#define SMEM_STEPS 88064

// ---------------- device scratch ----------------
__device__ __align__(16) __half g_xh[(size_t)BB * SS * II];
__device__ __align__(16) __half g_wih[H3 * II];
__device__ __align__(16) __half g_whh[H3 * HH];
__device__ __align__(16) float g_Xg[(size_t)SS * BB * H3];
__device__ __align__(16) float g_sx[SS * BB];
__device__ __align__(16) float g_hfp[2][BB * HH];
__device__ __align__(16) __half g_hh[2][BB * HH];
__device__ __align__(16) float g_ghp[2][(size_t)BB * H3];
__device__ float g_score[2][BB];
__device__ unsigned g_barc;
__device__ unsigned g_barg;

__device__ __forceinline__ void mma16816h(float* c, const uint32_t* a, uint32_t b0, uint32_t b1) {
    asm volatile(
        "mma.sync.aligned.m16n8k16.row.col.f32.f16.f16.f32 "
        "{%0,%1,%2,%3}, {%4,%5,%6,%7}, {%8,%9}, {%0,%1,%2,%3};\n"
        : "+f"(c[0]), "+f"(c[1]), "+f"(c[2]), "+f"(c[3])
        : "r"(a[0]), "r"(a[1]), "r"(a[2]), "r"(a[3]), "r"(b0), "r"(b1));
}

// device-wide barrier: arrival = one atomicAdd; poll = volatile load + nanosleep.
__device__ __forceinline__ void gbar(unsigned gen) {
    __syncthreads();
    if (threadIdx.x == 0) {
        __threadfence();
        unsigned t = atomicAdd(&g_barc, 1u) + 1u;
        if (t == gen * NPERS) {
            atomicExch(&g_barg, gen);
        } else {
            while (((volatile unsigned*)&g_barg)[0] < gen) __nanosleep(32);
        }
    }
    __syncthreads();
    __threadfence();
}

__device__ __forceinline__ float fsigmoid(float x) { return 1.f / (1.f + __expf(-x)); }
__device__ __forceinline__ float ftanh(float x) { float e = __expf(2.f * x); return 1.f - 2.f / (e + 1.f); }

// ---------------- init ----------------
__global__ void k_init() {
    int i = blockIdx.x * blockDim.x + threadIdx.x;
    if (i < BB * HH) {
        g_hfp[1][i] = 0.f;
        g_hh[1][i] = __float2half(0.f);
    }
    if (i < BB) g_score[1][i] = 0.f;
    if (i == 0) { g_barc = 0u; g_barg = 0u; }
}

// ---------------- fp32 -> fp16 ----------------
__global__ void k_split(const float* __restrict__ src, int n, int which) {
    __half* dst = (which == 0) ? g_xh : (which == 1) ? g_wih : g_whh;
    int i = blockIdx.x * blockDim.x + threadIdx.x;
    if (i < n) dst[i] = __float2half_rn(src[i]);
}

// ---------------- sx[t][b] = x[b,t,:] . W_att[0:I] (fp32 exact) ----------------
__global__ void k_sx(const float* __restrict__ x, const float* __restrict__ Watt) {
    int gw = (blockIdx.x * blockDim.x + threadIdx.x) >> 5;
    int lane = threadIdx.x & 31;
    if (gw >= SS * BB) return;
    int t = gw >> 7, b = gw & 127;
    const float* xr = x + ((size_t)b * SS + t) * II;
    float s = 0.f;
    for (int k = lane; k < II; k += 32) s += xr[k] * Watt[k];
    #pragma unroll
    for (int o = 16; o; o >>= 1) s += __shfl_xor_sync(0xffffffffu, s, o);
    if (!lane) g_sx[gw] = s;
}

// ---------------- precompute Xg[t][b][:] = x_t @ W_ih^T (single fp16 GEMM) ----------------
__global__ __launch_bounds__(256) void k_xg() {
    __shared__ __align__(16) __half As[2][128 * SA];
    __shared__ __align__(16) __half Bs[2][128 * SA];
    const int nblk = blockIdx.x, t = blockIdx.y;
    const int tid = threadIdx.x, w = tid >> 5, lane = tid & 31;
    const int wm = w & 3, wn = w >> 2, gid = lane >> 2, tig = lane & 3;
    const int ar = tid >> 1, ah = tid & 1;
    const size_t a_base = ((size_t)ar * SS + t) * II + ah * 8;
    const size_t b_base = ((size_t)(nblk * 128 + ar)) * II + ah * 8;

    float acc[2][8][4];
    #pragma unroll
    for (int i = 0; i < 2; ++i)
        #pragma unroll
        for (int j = 0; j < 8; ++j) { acc[i][j][0]=acc[i][j][1]=acc[i][j][2]=acc[i][j][3]=0.f; }

    *(uint4*)&As[0][ar * SA + ah * 8] = *(const uint4*)(g_xh + a_base);
    *(uint4*)&Bs[0][ar * SA + ah * 8] = *(const uint4*)(g_wih + b_base);
    __syncthreads();

    for (int it = 0; it < 32; ++it) {
        const int cur = it & 1;
        uint4 va, vb;
        const bool pf = (it + 1 < 32);
        if (pf) {
            int kk = (it + 1) << 4;
            va = *(const uint4*)(g_xh + a_base + kk);
            vb = *(const uint4*)(g_wih + b_base + kk);
        }
        uint32_t af[2][4];
        #pragma unroll
        for (int mt = 0; mt < 2; ++mt) {
            int r0 = wm * 32 + mt * 16;
            af[mt][0] = *(const uint32_t*)&As[cur][(r0 + gid) * SA + 2 * tig];
            af[mt][1] = *(const uint32_t*)&As[cur][(r0 + gid + 8) * SA + 2 * tig];
            af[mt][2] = *(const uint32_t*)&As[cur][(r0 + gid) * SA + 2 * tig + 8];
            af[mt][3] = *(const uint32_t*)&As[cur][(r0 + gid + 8) * SA + 2 * tig + 8];
        }
        #pragma unroll
        for (int nt = 0; nt < 8; ++nt) {
            int n0 = (wn * 8 + nt) * 8;
            uint32_t b0 = *(const uint32_t*)&Bs[cur][(n0 + gid) * SA + 2 * tig];
            uint32_t b1 = *(const uint32_t*)&Bs[cur][(n0 + gid) * SA + 2 * tig + 8];
            mma16816h(acc[0][nt], af[0], b0, b1);
            mma16816h(acc[1][nt], af[1], b0, b1);
        }
        __syncthreads();
        if (pf) {
            int nb = (it + 1) & 1;
            *(uint4*)&As[nb][ar * SA + ah * 8] = va;
            *(uint4*)&Bs[nb][ar * SA + ah * 8] = vb;
            __syncthreads();
        }
    }
    #pragma unroll
    for (int mt = 0; mt < 2; ++mt)
        #pragma unroll
        for (int nt = 0; nt < 8; ++nt) {
            int m = wm * 32 + mt * 16 + gid;
            int n = nblk * 128 + wn * 64 + nt * 8 + 2 * tig;
            size_t base = ((size_t)t * BB + m) * H3 + n;
            g_Xg[base]            = acc[mt][nt][0];
            g_Xg[base + 1]        = acc[mt][nt][1];
            g_Xg[base + 8 * H3]   = acc[mt][nt][2];
            g_Xg[base + 8 * H3+1] = acc[mt][nt][3];
        }
}

// ---------------- persistent step kernel ----------------
// 128 blocks = 64 n-tiles(48 cols) x 2 K-halves. W_hh tile (48x512 fp16) resident.
// Per step: h streamed in 8 chunks of K=64 (double buffer, 1 sync/chunk).
// Phase B: every block handles one batch row.
__global__ __launch_bounds__(256) void k_steps(const float* __restrict__ Watt,
                                               const float* __restrict__ b_ih,
                                               const float* __restrict__ b_hh,
                                               float* __restrict__ out, long long out_sz) {
    extern __shared__ __align__(16) char sm[];
    __half* Bsm = (__half*)(sm + TILB_OFF);   // 48 x BST2
    __half* Asm = (__half*)(sm + ABUF_OFF);   // 2 x 128 x AST
    float* sc   = (float*)(sm + SC_OFF);
    float* red  = (float*)(sm + RED_OFF);
    float* wsum = (float*)(sm + WSUM_OFF);

    const int bid = blockIdx.x;
    const int tid = threadIdx.x, w = tid >> 5, lane = tid & 31;
    const int wm = w & 3, wn = w >> 2, gid = lane >> 2, tig = lane & 3;

    const int nblk = bid & 63;       // 0..63 (48-col tile)
    const int kh = bid >> 6;         // 0..1  (K half)
    const int k0 = kh * 512;

    // resident W_hh tile: 48 rows x 512 k fp16
    #pragma unroll
    for (int it = 0; it < 12; ++it) {
        int idx = tid + it * 256;     // 0..3071 uint4
        int row = idx >> 6, col = idx & 63;
        *(uint4*)&Bsm[row * BST2 + col * 8] =
            *(const uint4*)(g_whh + (size_t)(nblk * 48 + row) * HH + k0 + col * 8);
    }

    // phase-B loop invariants
    const int j = tid * 4;
    float brz[8], bnn[8], wat[4];
    #pragma unroll
    for (int u = 0; u < 4; ++u) {
        brz[u]     = b_ih[j + u] + b_hh[j + u];
        brz[4 + u] = b_ih[HH + j + u] + b_hh[HH + j + u];
        bnn[u]     = b_ih[2 * HH + j + u];
        bnn[4 + u] = b_hh[2 * HH + j + u];
        wat[u]     = Watt[II + j + u];
    }

    const int arow = tid >> 1, ahalf = tid & 1;
    const size_t abase = (size_t)arow * HH + k0 + ahalf * 32;
    __syncthreads();

    unsigned gen = 0;
    for (int t = 0; t < SS; ++t) {
        const int pin = (t + 1) & 1, pout = t & 1;

        // ---------- phase A: ghp[kh] = h[:, k0:k0+512] @ W_hh[:, k0:k0+512]^T ----------
        {
            const __half* Ap = g_hh[pin];

            float acc[2][3][4];
            #pragma unroll
            for (int i = 0; i < 2; ++i)
                #pragma unroll
                for (int jj = 0; jj < 3; ++jj) { acc[i][jj][0]=acc[i][jj][1]=acc[i][jj][2]=acc[i][jj][3]=0.f; }

            // prologue: chunk 0 -> buf 0
            {
                const __half* s = Ap + abase;
                uint4 q0 = __ldcg((const uint4*)s);
                uint4 q1 = __ldcg((const uint4*)(s + 8));
                uint4 q2 = __ldcg((const uint4*)(s + 16));
                uint4 q3 = __ldcg((const uint4*)(s + 24));
                __half* d = Asm + arow * AST + ahalf * 32;
                *(uint4*)(d)      = q0;
                *(uint4*)(d + 8)  = q1;
                *(uint4*)(d + 16) = q2;
                *(uint4*)(d + 24) = q3;
            }
            __syncthreads();

            #pragma unroll 1
            for (int c = 0; c < 8; ++c) {
                const int cur = c & 1;
                uint4 q0, q1, q2, q3;
                const bool pf = (c < 7);
                if (pf) {
                    const __half* s = Ap + abase + (c + 1) * 64;
                    q0 = __ldcg((const uint4*)s);
                    q1 = __ldcg((const uint4*)(s + 8));
                    q2 = __ldcg((const uint4*)(s + 16));
                    q3 = __ldcg((const uint4*)(s + 24));
                }
                #pragma unroll
                for (int ks = 0; ks < 4; ++ks) {
                    const int ko = ks * 16;
                    uint32_t af[2][4];
                    #pragma unroll
                    for (int mt = 0; mt < 2; ++mt) {
                        const __half* ab = Asm + cur * (128 * AST) + (wm * 32 + mt * 16 + gid) * AST + 2 * tig + ko;
                        af[mt][0] = *(const uint32_t*)(ab);
                        af[mt][1] = *(const uint32_t*)(ab + 8 * AST);
                        af[mt][2] = *(const uint32_t*)(ab + 8);
                        af[mt][3] = *(const uint32_t*)(ab + 8 * AST + 8);
                    }
                    #pragma unroll
                    for (int nt = 0; nt < 3; ++nt) {
                        const __half* bb = Bsm + (wn * 24 + nt * 8 + gid) * BST2 + c * 64 + ko + 2 * tig;
                        uint32_t b0 = *(const uint32_t*)(bb);
                        uint32_t b1 = *(const uint32_t*)(bb + 8);
                        mma16816h(acc[0][nt], af[0], b0, b1);
                        mma16816h(acc[1][nt], af[1], b0, b1);
                    }
                }
                if (pf) {
                    __half* d = Asm + (cur ^ 1) * (128 * AST) + arow * AST + ahalf * 32;
                    *(uint4*)(d)      = q0;
                    *(uint4*)(d + 8)  = q1;
                    *(uint4*)(d + 16) = q2;
                    *(uint4*)(d + 24) = q3;
                }
                __syncthreads();
            }
            float* o = g_ghp[kh];
            #pragma unroll
            for (int mt = 0; mt < 2; ++mt)
                #pragma unroll
                for (int nt = 0; nt < 3; ++nt) {
                    int m = wm * 32 + mt * 16 + gid;
                    int n = nblk * 48 + wn * 24 + nt * 8 + 2 * tig;
                    size_t base = (size_t)m * H3 + n;
                    __stcg(&o[base],            acc[mt][nt][0]);
                    __stcg(&o[base + 1],        acc[mt][nt][1]);
                    __stcg(&o[base + 8 * H3],   acc[mt][nt][2]);
                    __stcg(&o[base + 8 * H3+1], acc[mt][nt][3]);
                }
        }
        gbar(++gen);

        // ---------- phase B: softmax + partial-sum + GRU update ----------
        {
            const int b = bid;
            if (tid < BB) {
                float v = __ldcg(&g_score[pin][tid]) + g_sx[t * BB + tid];
                sc[tid] = v;
                red[tid] = v;
            }
            __syncthreads();
            for (int s = 64; s; s >>= 1) { if (tid < s) red[tid] = fmaxf(red[tid], red[tid + s]); __syncthreads(); }
            float mx = red[0];
            __syncthreads();
            if (tid < BB) red[tid] = __expf(sc[tid] - mx);
            __syncthreads();
            for (int s = 64; s; s >>= 1) { if (tid < s) red[tid] += red[tid + s]; __syncthreads(); }
            const float att = __expf(sc[b] - mx) / red[0];

            const size_t rowb = (size_t)b * H3;
            float4 gr, gz, gn;
            {
                float4 v0, v1;
                v0 = __ldcg((const float4*)&g_ghp[0][rowb + j]);
                v1 = __ldcg((const float4*)&g_ghp[1][rowb + j]);
                gr = make_float4(v0.x+v1.x, v0.y+v1.y, v0.z+v1.z, v0.w+v1.w);
                v0 = __ldcg((const float4*)&g_ghp[0][rowb + HH + j]);
                v1 = __ldcg((const float4*)&g_ghp[1][rowb + HH + j]);
                gz = make_float4(v0.x+v1.x, v0.y+v1.y, v0.z+v1.z, v0.w+v1.w);
                v0 = __ldcg((const float4*)&g_ghp[0][rowb + 2*HH + j]);
                v1 = __ldcg((const float4*)&g_ghp[1][rowb + 2*HH + j]);
                gn = make_float4(v0.x+v1.x, v0.y+v1.y, v0.z+v1.z, v0.w+v1.w);
            }
            const size_t xgb = ((size_t)t * BB + b) * H3;
            float4 xr = *(const float4*)&g_Xg[xgb + j];
            float4 xz = *(const float4*)&g_Xg[xgb + HH + j];
            float4 xn = *(const float4*)&g_Xg[xgb + 2*HH + j];
            float4 hp = __ldcg((const float4*)&g_hfp[pin][(size_t)b * HH + j]);

            float hn[4], hdot = 0.f;
            #pragma unroll
            for (int u = 0; u < 4; ++u) {
                float r = fsigmoid(att * ((&xr.x)[u]) + (&gr.x)[u] + brz[u]);
                float z = fsigmoid(att * ((&xz.x)[u]) + (&gz.x)[u] + brz[4 + u]);
                float n = ftanh(att * ((&xn.x)[u]) + bnn[u] + r * ((&gn.x)[u] + bnn[4 + u]));
                float h = (1.f - z) * n + z * (&hp.x)[u];
                hn[u] = h;
                hdot += h * wat[u];
            }
            *(float4*)&out[((size_t)b * SS + t) * HH + j] = make_float4(hn[0], hn[1], hn[2], hn[3]);
            if (t == SS - 1 && out_sz >= (long long)BB * SS * HH + BB * HH)
                *(float4*)&out[(size_t)BB * SS * HH + (size_t)b * HH + j] = make_float4(hn[0], hn[1], hn[2], hn[3]);

            float4 hv = make_float4(hn[0], hn[1], hn[2], hn[3]);
            __stcg((float4*)&g_hfp[pout][(size_t)b * HH + j], hv);
            __half hh4[4];
            #pragma unroll
            for (int u = 0; u < 4; ++u) hh4[u] = __float2half_rn(hn[u]);
            __stcg((uint2*)&g_hh[pout][(size_t)b * HH + j], *(uint2*)hh4);

            #pragma unroll
            for (int o = 16; o; o >>= 1) hdot += __shfl_xor_sync(0xffffffffu, hdot, o);
            if ((tid & 31) == 0) wsum[tid >> 5] = hdot;
            __syncthreads();
            if (tid == 0) {
                float s = 0.f;
                #pragma unroll
                for (int i = 0; i < 8; ++i) s += wsum[i];
                __stcg(&g_score[pout][b], s);
            }
        }
        gbar(++gen);
    }
}

// ---------------- launch ----------------
extern "C" void kernel_launch(void* const* d_in, const int* in_sizes, int n_in,
                              void* d_out, int out_size) {
    const float* x    = (const float*)d_in[0];
    const float* Watt = (const float*)d_in[1];
    const float* Wih  = (const float*)d_in[3];
    const float* Whh  = (const float*)d_in[4];
    const float* b_ih = (const float*)d_in[5];
    const float* b_hh = (const float*)d_in[6];
    float* out = (float*)d_out;

    cudaFuncSetAttribute(k_steps, cudaFuncAttributeMaxDynamicSharedMemorySize, SMEM_STEPS);

    k_split<<<(BB * SS * II + 255) / 256, 256>>>(x, BB * SS * II, 0);
    k_split<<<(H3 * II + 255) / 256, 256>>>(Wih, H3 * II, 1);
    k_split<<<(H3 * HH + 255) / 256, 256>>>(Whh, H3 * HH, 2);
    k_sx<<<4096, 256>>>(x, Watt);
    k_init<<<512, 256>>>();
    k_xg<<<dim3(24, 256), 256>>>();
    k_steps<<<NPERS, 256, SMEM_STEPS>>>(Watt, b_ih, b_hh, out, (long long)out_size);
}